// round 1
// baseline (speedup 1.0000x reference)
#include <cuda_runtime.h>
#include <cstdint>

// Problem constants (from reference: N=100000, E=1600000, IN_DIM=128, H=4, D=16)
#define MAX_N 100000
#define HD    64      // H*D output width
#define KD    128     // input dim
#define NHEAD 4

// ---------------- device scratch (static allocation; no cudaMalloc allowed) ----
__device__ float g_h  [MAX_N * HD];   // projected features [N,64]
__device__ float g_ss [MAX_N * NHEAD];// per-node src scores [N,4]
__device__ float g_sd [MAX_N * NHEAD];// per-node dst scores [N,4]
__device__ float g_sum[MAX_N * NHEAD];// softmax denominators -> reciprocals [N,4]

// ---------------- init: zero output + denominators --------------------------
__global__ void k_init(float* __restrict__ out, int n) {
    int i = blockIdx.x * blockDim.x + threadIdx.x;
    if (i < n * HD) out[i] = 0.f;
    if (i < n * NHEAD) g_sum[i] = 0.f;
}

// ---------------- GEMM: h = x @ W^T  (fp32, smem tiled, 4x4 micro-tile) -----
// Block: 256 threads = 16x16, tile 64 rows x 64 cols x K=128 (whole K).
// xs: [64][132] (pad 132 -> 4-row step shifts banks by 16, conflict-free for
//     the 2 distinct row-groups per warp). wt: W transposed [128][68] so the
//     b-operand is a contiguous float4 per thread (conflict-free LDS.128).
constexpr int XS_STRIDE   = 132;
constexpr int WT_STRIDE   = 68;
constexpr int GEMM_SMEM_F = 64 * XS_STRIDE + 128 * WT_STRIDE; // 17152 floats
constexpr int GEMM_SMEM_B = GEMM_SMEM_F * 4;                  // 68608 bytes

__global__ void __launch_bounds__(256) k_gemm(const float* __restrict__ x,
                                              const float* __restrict__ W,
                                              int n) {
    extern __shared__ float sm[];
    float* xs = sm;                    // [64][XS_STRIDE]
    float* wt = sm + 64 * XS_STRIDE;   // [128][WT_STRIDE]
    const int tid  = threadIdx.x;
    const int row0 = blockIdx.x * 64;

    // Load W (64x128) transposed into wt[k][o]. 2048 float4 total.
    for (int i = tid; i < 2048; i += 256) {
        int o = i >> 5, k4 = i & 31;
        float4 v = ((const float4*)W)[i];      // W[o][k4*4 .. k4*4+3]
        wt[(k4 * 4 + 0) * WT_STRIDE + o] = v.x;
        wt[(k4 * 4 + 1) * WT_STRIDE + o] = v.y;
        wt[(k4 * 4 + 2) * WT_STRIDE + o] = v.z;
        wt[(k4 * 4 + 3) * WT_STRIDE + o] = v.w;
    }
    // Load x tile (64 rows x 128) into xs.
    for (int i = tid; i < 2048; i += 256) {
        int r = i >> 5, k4 = i & 31;
        int row = row0 + r;
        float4 v = (row < n) ? ((const float4*)x)[row * 32 + k4]
                             : make_float4(0.f, 0.f, 0.f, 0.f);
        *(float4*)&xs[r * XS_STRIDE + k4 * 4] = v;
    }
    __syncthreads();

    const int ty = tid >> 4, tx = tid & 15;
    float acc[4][4] = {};
    const float* xp = xs + (ty * 4) * XS_STRIDE;

#pragma unroll 4
    for (int k = 0; k < KD; k++) {
        float4 b = *(const float4*)&wt[k * WT_STRIDE + tx * 4];
        float a[4];
#pragma unroll
        for (int i = 0; i < 4; i++) a[i] = xp[i * XS_STRIDE + k];
#pragma unroll
        for (int i = 0; i < 4; i++) {
            acc[i][0] = fmaf(a[i], b.x, acc[i][0]);
            acc[i][1] = fmaf(a[i], b.y, acc[i][1]);
            acc[i][2] = fmaf(a[i], b.z, acc[i][2]);
            acc[i][3] = fmaf(a[i], b.w, acc[i][3]);
        }
    }

#pragma unroll
    for (int i = 0; i < 4; i++) {
        int row = row0 + ty * 4 + i;
        if (row < n) {
            float4 o4 = make_float4(acc[i][0], acc[i][1], acc[i][2], acc[i][3]);
            *(float4*)&g_h[row * HD + tx * 4] = o4;
        }
    }
}

// ---------------- per-node attention scores: s = h . a  ----------------------
__global__ void k_scores(const float* __restrict__ a_src,
                         const float* __restrict__ a_dst, int n) {
    int node = blockIdx.x * blockDim.x + threadIdx.x;
    if (node >= n) return;
    const float4* hr  = (const float4*)(g_h + node * HD);
    const float4* as4 = (const float4*)a_src;  // [4][16] row-major
    const float4* ad4 = (const float4*)a_dst;
#pragma unroll
    for (int h = 0; h < NHEAD; h++) {
        float s1 = 0.f, s2 = 0.f;
#pragma unroll
        for (int q = 0; q < 4; q++) {
            float4 hv = hr[h * 4 + q];
            float4 a  = __ldg(&as4[h * 4 + q]);
            float4 b  = __ldg(&ad4[h * 4 + q]);
            s1 += hv.x * a.x + hv.y * a.y + hv.z * a.z + hv.w * a.w;
            s2 += hv.x * b.x + hv.y * b.y + hv.z * b.z + hv.w * b.w;
        }
        g_ss[node * NHEAD + h] = s1;
        g_sd[node * NHEAD + h] = s2;
    }
}

// ---------------- edge pass 1: softmax denominators --------------------------
// Softmax shift-invariance: exp(e - m)/sum(exp(e - m)) == exp(e)/sum(exp(e)),
// and with |e| small the 1e-9 clamp never changes which branch binds, so we
// can skip the reference's segment-max pass entirely.
__global__ void k_edge_sum(const int* __restrict__ ei, int E) {
    unsigned tid = blockIdx.x * blockDim.x + threadIdx.x;
    unsigned e = tid >> 2;
    if (e >= (unsigned)E) return;
    int hh  = tid & 3;
    int src = ei[e];
    int dst = ei[E + e];
    float s = g_ss[src * NHEAD + hh] + g_sd[dst * NHEAD + hh];
    s = (s > 0.f) ? s : 0.2f * s;           // leaky_relu(0.2)
    atomicAdd(&g_sum[dst * NHEAD + hh], __expf(s));
}

// ---------------- reciprocal of denominators --------------------------------
__global__ void k_rcp(int n) {
    int i = blockIdx.x * blockDim.x + threadIdx.x;
    if (i < n * NHEAD) g_sum[i] = 1.f / fmaxf(g_sum[i], 1e-9f);
}

// ---------------- edge pass 2: gather-scale-scatter --------------------------
// 16 threads per edge; each owns one float4 of the 64-wide message and emits
// a single red.global.add.v4.f32 (16B vector reduction, sm_90+).
__global__ void k_scatter(const int* __restrict__ ei, float* __restrict__ out,
                          int E) {
    unsigned tid = blockIdx.x * blockDim.x + threadIdx.x;
    unsigned e = tid >> 4;
    if (e >= (unsigned)E) return;
    int l    = tid & 15;
    int head = l >> 2;
    int q    = l & 3;
    int src = ei[e];
    int dst = ei[E + e];
    float s = g_ss[src * NHEAD + head] + g_sd[dst * NHEAD + head];
    s = (s > 0.f) ? s : 0.2f * s;
    float alpha = __expf(s) * g_sum[dst * NHEAD + head];
    float4 hv = ((const float4*)g_h)[src * 16 + head * 4 + q];
    float* p = out + dst * HD + head * 16 + q * 4;
    asm volatile("red.global.add.v4.f32 [%0], {%1, %2, %3, %4};"
                 :: "l"(p), "f"(hv.x * alpha), "f"(hv.y * alpha),
                    "f"(hv.z * alpha), "f"(hv.w * alpha)
                 : "memory");
}

// ---------------- launch ------------------------------------------------------
extern "C" void kernel_launch(void* const* d_in, const int* in_sizes, int n_in,
                              void* d_out, int out_size) {
    const float* x     = (const float*)d_in[0];
    const float* W     = (const float*)d_in[1];
    const float* a_src = (const float*)d_in[2];
    const float* a_dst = (const float*)d_in[3];
    const int*   ei    = (const int*)d_in[4];
    float*       out   = (float*)d_out;

    const int n = in_sizes[0] / KD;       // 100000
    const int E = in_sizes[4] / 2;        // 1600000

    static bool attr_set = false;
    if (!attr_set) {
        cudaFuncSetAttribute(k_gemm, cudaFuncAttributeMaxDynamicSharedMemorySize,
                             GEMM_SMEM_B);
        attr_set = true;
    }

    k_init<<<(n * HD + 255) / 256, 256>>>(out, n);
    k_gemm<<<(n + 63) / 64, 256, GEMM_SMEM_B>>>(x, W, n);
    k_scores<<<(n + 255) / 256, 256>>>(a_src, a_dst, n);
    k_edge_sum<<<(E * 4 + 255) / 256, 256>>>(ei, E);
    k_rcp<<<(n * NHEAD + 255) / 256, 256>>>(n);
    k_scatter<<<(E * 16 + 255) / 256, 256>>>(ei, out, E);
}

// round 2
// speedup vs baseline: 1.1889x; 1.1889x over previous
#include <cuda_runtime.h>
#include <cstdint>

// Problem constants (N=100000, E=1600000, IN_DIM=128, H=4, D=16)
#define MAX_N 100000
#define MAX_E 1600000
#define HD    64
#define KD    128
#define NHEAD 4

// ---------------- device scratch (static; no cudaMalloc allowed) -------------
__device__ float4 g_h4 [MAX_N * 16];     // projected features [N,64] as float4
__device__ float4 g_ss [MAX_N];          // per-node src scores [N,4]
__device__ float4 g_sd [MAX_N];          // per-node dst scores [N,4]
__device__ int    g_cnt[MAX_N];          // in-degree histogram
__device__ int    g_off[MAX_N];          // exclusive prefix (mutated by permute)
__device__ int    g_bsum[128];           // scan block sums
__device__ int    g_boff[128];           // scan block offsets
__device__ int    g_src_sorted[MAX_E];   // src node id, binned by dst
__device__ float4 g_exp_sorted[MAX_E];   // exp(leaky(e)) per head, binned by dst

// ---------------- init: zero histogram ---------------------------------------
__global__ void k_init(int n) {
    int i = blockIdx.x * blockDim.x + threadIdx.x;
    if (i < n) g_cnt[i] = 0;
}

// ---------------- GEMM: h = x @ W^T  (fp32, smem tiled, 4x4 micro-tile) -----
constexpr int XS_STRIDE   = 132;
constexpr int WT_STRIDE   = 68;
constexpr int GEMM_SMEM_F = 64 * XS_STRIDE + 128 * WT_STRIDE;
constexpr int GEMM_SMEM_B = GEMM_SMEM_F * 4;

__global__ void __launch_bounds__(256) k_gemm(const float* __restrict__ x,
                                              const float* __restrict__ W,
                                              int n) {
    extern __shared__ float sm[];
    float* xs = sm;
    float* wt = sm + 64 * XS_STRIDE;
    const int tid  = threadIdx.x;
    const int row0 = blockIdx.x * 64;

    for (int i = tid; i < 2048; i += 256) {
        int o = i >> 5, k4 = i & 31;
        float4 v = ((const float4*)W)[i];
        wt[(k4 * 4 + 0) * WT_STRIDE + o] = v.x;
        wt[(k4 * 4 + 1) * WT_STRIDE + o] = v.y;
        wt[(k4 * 4 + 2) * WT_STRIDE + o] = v.z;
        wt[(k4 * 4 + 3) * WT_STRIDE + o] = v.w;
    }
    for (int i = tid; i < 2048; i += 256) {
        int r = i >> 5, k4 = i & 31;
        int row = row0 + r;
        float4 v = (row < n) ? ((const float4*)x)[row * 32 + k4]
                             : make_float4(0.f, 0.f, 0.f, 0.f);
        *(float4*)&xs[r * XS_STRIDE + k4 * 4] = v;
    }
    __syncthreads();

    const int ty = tid >> 4, tx = tid & 15;
    float acc[4][4] = {};
    const float* xp = xs + (ty * 4) * XS_STRIDE;

#pragma unroll 4
    for (int k = 0; k < KD; k++) {
        float4 b = *(const float4*)&wt[k * WT_STRIDE + tx * 4];
        float a[4];
#pragma unroll
        for (int i = 0; i < 4; i++) a[i] = xp[i * XS_STRIDE + k];
#pragma unroll
        for (int i = 0; i < 4; i++) {
            acc[i][0] = fmaf(a[i], b.x, acc[i][0]);
            acc[i][1] = fmaf(a[i], b.y, acc[i][1]);
            acc[i][2] = fmaf(a[i], b.z, acc[i][2]);
            acc[i][3] = fmaf(a[i], b.w, acc[i][3]);
        }
    }

#pragma unroll
    for (int i = 0; i < 4; i++) {
        int row = row0 + ty * 4 + i;
        if (row < n)
            g_h4[row * 16 + tx] = make_float4(acc[i][0], acc[i][1], acc[i][2], acc[i][3]);
    }
}

// ---------------- per-node attention scores ----------------------------------
__global__ void k_scores(const float* __restrict__ a_src,
                         const float* __restrict__ a_dst, int n) {
    int node = blockIdx.x * blockDim.x + threadIdx.x;
    if (node >= n) return;
    const float4* as4 = (const float4*)a_src;
    const float4* ad4 = (const float4*)a_dst;
    float s1[NHEAD], s2[NHEAD];
#pragma unroll
    for (int h = 0; h < NHEAD; h++) {
        s1[h] = 0.f; s2[h] = 0.f;
#pragma unroll
        for (int q = 0; q < 4; q++) {
            float4 hv = g_h4[node * 16 + h * 4 + q];
            float4 a  = __ldg(&as4[h * 4 + q]);
            float4 b  = __ldg(&ad4[h * 4 + q]);
            s1[h] += hv.x * a.x + hv.y * a.y + hv.z * a.z + hv.w * a.w;
            s2[h] += hv.x * b.x + hv.y * b.y + hv.z * b.z + hv.w * b.w;
        }
    }
    g_ss[node] = make_float4(s1[0], s1[1], s1[2], s1[3]);
    g_sd[node] = make_float4(s2[0], s2[1], s2[2], s2[3]);
}

// ---------------- in-degree histogram ----------------------------------------
__global__ void k_hist(const int* __restrict__ ei, int E) {
    int e = blockIdx.x * blockDim.x + threadIdx.x;
    if (e < E) atomicAdd(&g_cnt[ei[E + e]], 1);
}

// ---------------- exclusive scan (3 kernels; chunk = 1024) -------------------
__global__ void k_scan_a(int n) {                 // block totals
    __shared__ int warp_tot[8];
    int b = blockIdx.x, t = threadIdx.x;
    int idx0 = b * 1024 + t * 4;
    int s = 0;
#pragma unroll
    for (int j = 0; j < 4; j++) { int i = idx0 + j; if (i < n) s += g_cnt[i]; }
#pragma unroll
    for (int d = 16; d; d >>= 1) s += __shfl_down_sync(0xffffffffu, s, d);
    if ((t & 31) == 0) warp_tot[t >> 5] = s;
    __syncthreads();
    if (t == 0) {
        int tot = 0;
#pragma unroll
        for (int w = 0; w < 8; w++) tot += warp_tot[w];
        g_bsum[b] = tot;
    }
}

__global__ void k_scan_b(int nb) {                // scan block totals (1 block)
    __shared__ int wt[4];
    int t = threadIdx.x;                          // 128 threads
    int v = (t < nb) ? g_bsum[t] : 0;
    int lane = t & 31, w = t >> 5;
    int inc = v;
#pragma unroll
    for (int d = 1; d < 32; d <<= 1) {
        int o = __shfl_up_sync(0xffffffffu, inc, d);
        if (lane >= d) inc += o;
    }
    if (lane == 31) wt[w] = inc;
    __syncthreads();
    if (t == 0) {
        int s = 0;
#pragma unroll
        for (int i = 0; i < 4; i++) { int x = wt[i]; wt[i] = s; s += x; }
    }
    __syncthreads();
    int excl = wt[w] + inc - v;
    if (t < nb) g_boff[t] = excl;
}

__global__ void k_scan_c(int n) {                 // final exclusive scan
    __shared__ int warp_pre[8];
    __shared__ int blk_base;
    int b = blockIdx.x, t = threadIdx.x;
    int idx0 = b * 1024 + t * 4;
    int v[4];
#pragma unroll
    for (int j = 0; j < 4; j++) { int i = idx0 + j; v[j] = (i < n) ? g_cnt[i] : 0; }
    int tsum = v[0] + v[1] + v[2] + v[3];
    int lane = t & 31, w = t >> 5;
    int inc = tsum;
#pragma unroll
    for (int d = 1; d < 32; d <<= 1) {
        int o = __shfl_up_sync(0xffffffffu, inc, d);
        if (lane >= d) inc += o;
    }
    if (lane == 31) warp_pre[w] = inc;
    __syncthreads();
    if (t == 0) {
        int s = 0;
#pragma unroll
        for (int ww = 0; ww < 8; ww++) { int x = warp_pre[ww]; warp_pre[ww] = s; s += x; }
        blk_base = g_boff[b];
    }
    __syncthreads();
    int excl = blk_base + warp_pre[w] + (inc - tsum);
#pragma unroll
    for (int j = 0; j < 4; j++) {
        int i = idx0 + j;
        if (i < n) g_off[i] = excl;
        excl += v[j];
    }
}

// ---------------- permute: bin edges by dst, precompute exp(leaky(e)) --------
// After this pass, g_off[i] == end offset of node i (start = g_off[i-1]).
__global__ void k_permute(const int* __restrict__ ei, int E) {
    int e = blockIdx.x * blockDim.x + threadIdx.x;
    if (e >= E) return;
    int src = ei[e];
    int dst = ei[E + e];
    float4 s4 = g_ss[src];
    float4 d4 = g_sd[dst];
    float4 ee;
    float s;
    s = s4.x + d4.x; s = (s > 0.f) ? s : 0.2f * s; ee.x = __expf(s);
    s = s4.y + d4.y; s = (s > 0.f) ? s : 0.2f * s; ee.y = __expf(s);
    s = s4.z + d4.z; s = (s > 0.f) ? s : 0.2f * s; ee.z = __expf(s);
    s = s4.w + d4.w; s = (s > 0.f) ? s : 0.2f * s; ee.w = __expf(s);
    int pos = atomicAdd(&g_off[dst], 1);
    g_src_sorted[pos] = src;
    g_exp_sorted[pos] = ee;
}

// ---------------- pull accumulate: 16 threads per node, no atomics -----------
__global__ void k_accum(float* __restrict__ out, int n) {
    int g = blockIdx.x * blockDim.x + threadIdx.x;
    int node = g >> 4;
    if (node >= n) return;
    int l = g & 15;            // l = head*4 + q
    int head = l >> 2;
    int start = node ? g_off[node - 1] : 0;   // g_off holds end offsets now
    int end   = g_off[node];

    float4 acc = make_float4(0.f, 0.f, 0.f, 0.f);
    float sume = 0.f;
    const float* exps = (const float*)g_exp_sorted;
    for (int e = start; e < end; e++) {
        int   src  = __ldg(&g_src_sorted[e]);
        float expe = __ldg(&exps[e * 4 + head]);
        float4 hv  = g_h4[src * 16 + l];
        acc.x = fmaf(hv.x, expe, acc.x);
        acc.y = fmaf(hv.y, expe, acc.y);
        acc.z = fmaf(hv.z, expe, acc.z);
        acc.w = fmaf(hv.w, expe, acc.w);
        sume += expe;
    }
    float r = 1.f / fmaxf(sume, 1e-9f);
    ((float4*)out)[node * 16 + l] =
        make_float4(acc.x * r, acc.y * r, acc.z * r, acc.w * r);
}

// ---------------- launch ------------------------------------------------------
extern "C" void kernel_launch(void* const* d_in, const int* in_sizes, int n_in,
                              void* d_out, int out_size) {
    const float* x     = (const float*)d_in[0];
    const float* W     = (const float*)d_in[1];
    const float* a_src = (const float*)d_in[2];
    const float* a_dst = (const float*)d_in[3];
    const int*   ei    = (const int*)d_in[4];
    float*       out   = (float*)d_out;

    const int n = in_sizes[0] / KD;
    const int E = in_sizes[4] / 2;
    const int nb = (n + 1023) / 1024;     // scan blocks (<=128)

    static bool attr_set = false;
    if (!attr_set) {
        cudaFuncSetAttribute(k_gemm, cudaFuncAttributeMaxDynamicSharedMemorySize,
                             GEMM_SMEM_B);
        attr_set = true;
    }

    k_init   <<<(n + 255) / 256, 256>>>(n);
    k_gemm   <<<(n + 63) / 64, 256, GEMM_SMEM_B>>>(x, W, n);
    k_scores <<<(n + 255) / 256, 256>>>(a_src, a_dst, n);
    k_hist   <<<(E + 255) / 256, 256>>>(ei, E);
    k_scan_a <<<nb, 256>>>(n);
    k_scan_b <<<1, 128>>>(nb);
    k_scan_c <<<nb, 256>>>(n);
    k_permute<<<(E + 255) / 256, 256>>>(ei, E);
    k_accum  <<<(n * 16 + 255) / 256, 256>>>(out, n);
}

// round 3
// speedup vs baseline: 1.2165x; 1.0232x over previous
#include <cuda_runtime.h>
#include <cstdint>

// Problem constants (N=100000, E=1600000, IN_DIM=128, H=4, D=16)
#define MAX_N 100000
#define MAX_E 1600000
#define HD    64
#define KD    128
#define NHEAD 4

// ---------------- device scratch (static; no cudaMalloc allowed) -------------
__device__ float4 g_h4 [MAX_N * 16];     // projected features [N,64] as float4
__device__ float4 g_ss [MAX_N];          // per-node src scores [N,4]
__device__ float4 g_sd [MAX_N];          // per-node dst scores [N,4]
__device__ int    g_cnt[MAX_N];          // in-degree histogram
__device__ int    g_off[MAX_N];          // exclusive prefix (mutated by permute)
__device__ int    g_bsum[128];           // scan block sums
__device__ int    g_boff[128];           // scan block offsets
__device__ int    g_src_sorted[MAX_E];   // src node id, binned by dst
__device__ float4 g_exp_sorted[MAX_E];   // exp(leaky(e)) per head, binned by dst

// ---------------- init: zero histogram ---------------------------------------
__global__ void k_init(int n) {
    int i = blockIdx.x * blockDim.x + threadIdx.x;
    if (i < n) g_cnt[i] = 0;
}

// ---------------- GEMM: h = x @ W^T  + fused attention scores ---------------
constexpr int XS_STRIDE   = 132;
constexpr int WT_STRIDE   = 68;
constexpr int GEMM_SMEM_F = 64 * XS_STRIDE + 128 * WT_STRIDE;
constexpr int GEMM_SMEM_B = GEMM_SMEM_F * 4;

__global__ void __launch_bounds__(256) k_gemm(const float* __restrict__ x,
                                              const float* __restrict__ W,
                                              const float* __restrict__ a_src,
                                              const float* __restrict__ a_dst,
                                              int n) {
    extern __shared__ float sm[];
    float* xs = sm;
    float* wt = sm + 64 * XS_STRIDE;
    const int tid  = threadIdx.x;
    const int row0 = blockIdx.x * 64;

    for (int i = tid; i < 2048; i += 256) {
        int o = i >> 5, k4 = i & 31;
        float4 v = ((const float4*)W)[i];
        wt[(k4 * 4 + 0) * WT_STRIDE + o] = v.x;
        wt[(k4 * 4 + 1) * WT_STRIDE + o] = v.y;
        wt[(k4 * 4 + 2) * WT_STRIDE + o] = v.z;
        wt[(k4 * 4 + 3) * WT_STRIDE + o] = v.w;
    }
    for (int i = tid; i < 2048; i += 256) {
        int r = i >> 5, k4 = i & 31;
        int row = row0 + r;
        float4 v = (row < n) ? ((const float4*)x)[row * 32 + k4]
                             : make_float4(0.f, 0.f, 0.f, 0.f);
        *(float4*)&xs[r * XS_STRIDE + k4 * 4] = v;
    }
    __syncthreads();

    const int ty = tid >> 4, tx = tid & 15;
    float acc[4][4] = {};
    const float* xp = xs + (ty * 4) * XS_STRIDE;

#pragma unroll 4
    for (int k = 0; k < KD; k++) {
        float4 b = *(const float4*)&wt[k * WT_STRIDE + tx * 4];
        float a[4];
#pragma unroll
        for (int i = 0; i < 4; i++) a[i] = xp[i * XS_STRIDE + k];
#pragma unroll
        for (int i = 0; i < 4; i++) {
            acc[i][0] = fmaf(a[i], b.x, acc[i][0]);
            acc[i][1] = fmaf(a[i], b.y, acc[i][1]);
            acc[i][2] = fmaf(a[i], b.z, acc[i][2]);
            acc[i][3] = fmaf(a[i], b.w, acc[i][3]);
        }
    }

    // Fused epilogue: write h, plus per-(row,head) scores s1 = h.a_src, s2 = h.a_dst.
    // Thread tx owns cols tx*4..tx*4+3 (head = tx>>2); reduce over the 4 lanes
    // of a head group with shfl_xor(1,2) — lanes stay inside one warp.
    float4 av = __ldg(&((const float4*)a_src)[tx]);
    float4 bv = __ldg(&((const float4*)a_dst)[tx]);
    int head = tx >> 2;
#pragma unroll
    for (int i = 0; i < 4; i++) {
        int row = row0 + ty * 4 + i;
        float s1 = acc[i][0] * av.x + acc[i][1] * av.y + acc[i][2] * av.z + acc[i][3] * av.w;
        float s2 = acc[i][0] * bv.x + acc[i][1] * bv.y + acc[i][2] * bv.z + acc[i][3] * bv.w;
        s1 += __shfl_xor_sync(0xffffffffu, s1, 1);
        s1 += __shfl_xor_sync(0xffffffffu, s1, 2);
        s2 += __shfl_xor_sync(0xffffffffu, s2, 1);
        s2 += __shfl_xor_sync(0xffffffffu, s2, 2);
        if (row < n) {
            g_h4[row * 16 + tx] = make_float4(acc[i][0], acc[i][1], acc[i][2], acc[i][3]);
            if ((tx & 3) == 0) {
                ((float*)g_ss)[row * 4 + head] = s1;
                ((float*)g_sd)[row * 4 + head] = s2;
            }
        }
    }
}

// ---------------- in-degree histogram (4 independent REDs per thread) --------
__global__ void k_hist(const int* __restrict__ ei, int E) {
    int t = blockIdx.x * blockDim.x + threadIdx.x;
    if ((E & 3) == 0) {
        int i4 = t * 4;
        if (i4 >= E) return;
        int4 d = *(const int4*)&ei[E + i4];
        atomicAdd(&g_cnt[d.x], 1);
        atomicAdd(&g_cnt[d.y], 1);
        atomicAdd(&g_cnt[d.z], 1);
        atomicAdd(&g_cnt[d.w], 1);
    } else {
        int i4 = t * 4;
#pragma unroll
        for (int j = 0; j < 4; j++)
            if (i4 + j < E) atomicAdd(&g_cnt[ei[E + i4 + j]], 1);
    }
}

// ---------------- exclusive scan (3 kernels; chunk = 1024) -------------------
__global__ void k_scan_a(int n) {                 // block totals
    __shared__ int warp_tot[8];
    int b = blockIdx.x, t = threadIdx.x;
    int idx0 = b * 1024 + t * 4;
    int s = 0;
#pragma unroll
    for (int j = 0; j < 4; j++) { int i = idx0 + j; if (i < n) s += g_cnt[i]; }
#pragma unroll
    for (int d = 16; d; d >>= 1) s += __shfl_down_sync(0xffffffffu, s, d);
    if ((t & 31) == 0) warp_tot[t >> 5] = s;
    __syncthreads();
    if (t == 0) {
        int tot = 0;
#pragma unroll
        for (int w = 0; w < 8; w++) tot += warp_tot[w];
        g_bsum[b] = tot;
    }
}

__global__ void k_scan_b(int nb) {                // scan block totals (1 block)
    __shared__ int wt[4];
    int t = threadIdx.x;                          // 128 threads
    int v = (t < nb) ? g_bsum[t] : 0;
    int lane = t & 31, w = t >> 5;
    int inc = v;
#pragma unroll
    for (int d = 1; d < 32; d <<= 1) {
        int o = __shfl_up_sync(0xffffffffu, inc, d);
        if (lane >= d) inc += o;
    }
    if (lane == 31) wt[w] = inc;
    __syncthreads();
    if (t == 0) {
        int s = 0;
#pragma unroll
        for (int i = 0; i < 4; i++) { int x = wt[i]; wt[i] = s; s += x; }
    }
    __syncthreads();
    int excl = wt[w] + inc - v;
    if (t < nb) g_boff[t] = excl;
}

__global__ void k_scan_c(int n) {                 // final exclusive scan
    __shared__ int warp_pre[8];
    __shared__ int blk_base;
    int b = blockIdx.x, t = threadIdx.x;
    int idx0 = b * 1024 + t * 4;
    int v[4];
#pragma unroll
    for (int j = 0; j < 4; j++) { int i = idx0 + j; v[j] = (i < n) ? g_cnt[i] : 0; }
    int tsum = v[0] + v[1] + v[2] + v[3];
    int lane = t & 31, w = t >> 5;
    int inc = tsum;
#pragma unroll
    for (int d = 1; d < 32; d <<= 1) {
        int o = __shfl_up_sync(0xffffffffu, inc, d);
        if (lane >= d) inc += o;
    }
    if (lane == 31) warp_pre[w] = inc;
    __syncthreads();
    if (t == 0) {
        int s = 0;
#pragma unroll
        for (int ww = 0; ww < 8; ww++) { int x = warp_pre[ww]; warp_pre[ww] = s; s += x; }
        blk_base = g_boff[b];
    }
    __syncthreads();
    int excl = blk_base + warp_pre[w] + (inc - tsum);
#pragma unroll
    for (int j = 0; j < 4; j++) {
        int i = idx0 + j;
        if (i < n) g_off[i] = excl;
        excl += v[j];
    }
}

// ---------------- permute: bin edges by dst, 2 edges per thread for MLP ------
// After this pass, g_off[i] == end offset of node i (start = g_off[i-1]).
__device__ __forceinline__ void permute_one(int src, int dst) {
    float4 s4 = g_ss[src];
    float4 d4 = g_sd[dst];
    float4 ee;
    float s;
    s = s4.x + d4.x; s = (s > 0.f) ? s : 0.2f * s; ee.x = __expf(s);
    s = s4.y + d4.y; s = (s > 0.f) ? s : 0.2f * s; ee.y = __expf(s);
    s = s4.z + d4.z; s = (s > 0.f) ? s : 0.2f * s; ee.z = __expf(s);
    s = s4.w + d4.w; s = (s > 0.f) ? s : 0.2f * s; ee.w = __expf(s);
    int pos = atomicAdd(&g_off[dst], 1);
    g_src_sorted[pos] = src;
    g_exp_sorted[pos] = ee;
}

__global__ void k_permute(const int* __restrict__ ei, int E) {
    int p = blockIdx.x * blockDim.x + threadIdx.x;
    if ((E & 1) == 0) {
        int e0 = p * 2;
        if (e0 >= E) return;
        int2 sv = *(const int2*)&ei[e0];
        int2 dv = *(const int2*)&ei[E + e0];
        permute_one(sv.x, dv.x);
        permute_one(sv.y, dv.y);
    } else {
        int e0 = p * 2;
#pragma unroll
        for (int j = 0; j < 2; j++)
            if (e0 + j < E) permute_one(ei[e0 + j], ei[E + e0 + j]);
    }
}

// ---------------- pull accumulate: one warp per node, no atomics -------------
// 32 lanes = 2 edge-slots x 16 components; unroll 2 -> 4 edges in flight.
__global__ void k_accum(float* __restrict__ out, int n) {
    int warp = (blockIdx.x * blockDim.x + threadIdx.x) >> 5;
    if (warp >= n) return;
    int lane = threadIdx.x & 31;
    int j    = lane >> 4;          // edge slot 0/1
    int l    = lane & 15;          // component: head*4 + q
    int head = l >> 2;
    int start = warp ? g_off[warp - 1] : 0;   // g_off holds end offsets now
    int end   = g_off[warp];

    float4 acc = make_float4(0.f, 0.f, 0.f, 0.f);
    float sume = 0.f;
    const float* exps = (const float*)g_exp_sorted;
#pragma unroll 2
    for (int e = start + j; e < end; e += 2) {
        int   src  = __ldg(&g_src_sorted[e]);
        float expe = __ldg(&exps[e * 4 + head]);
        float4 hv  = g_h4[src * 16 + l];
        acc.x = fmaf(hv.x, expe, acc.x);
        acc.y = fmaf(hv.y, expe, acc.y);
        acc.z = fmaf(hv.z, expe, acc.z);
        acc.w = fmaf(hv.w, expe, acc.w);
        sume += expe;
    }
    // combine the two edge slots
    acc.x += __shfl_xor_sync(0xffffffffu, acc.x, 16);
    acc.y += __shfl_xor_sync(0xffffffffu, acc.y, 16);
    acc.z += __shfl_xor_sync(0xffffffffu, acc.z, 16);
    acc.w += __shfl_xor_sync(0xffffffffu, acc.w, 16);
    sume  += __shfl_xor_sync(0xffffffffu, sume, 16);
    if (j == 0) {
        float r = 1.f / fmaxf(sume, 1e-9f);
        ((float4*)out)[warp * 16 + l] =
            make_float4(acc.x * r, acc.y * r, acc.z * r, acc.w * r);
    }
}

// ---------------- launch ------------------------------------------------------
extern "C" void kernel_launch(void* const* d_in, const int* in_sizes, int n_in,
                              void* d_out, int out_size) {
    const float* x     = (const float*)d_in[0];
    const float* W     = (const float*)d_in[1];
    const float* a_src = (const float*)d_in[2];
    const float* a_dst = (const float*)d_in[3];
    const int*   ei    = (const int*)d_in[4];
    float*       out   = (float*)d_out;

    const int n = in_sizes[0] / KD;
    const int E = in_sizes[4] / 2;
    const int nb = (n + 1023) / 1024;     // scan blocks (<=128)

    static bool attr_set = false;
    if (!attr_set) {
        cudaFuncSetAttribute(k_gemm, cudaFuncAttributeMaxDynamicSharedMemorySize,
                             GEMM_SMEM_B);
        attr_set = true;
    }

    k_init   <<<(n + 255) / 256, 256>>>(n);
    k_gemm   <<<(n + 63) / 64, 256, GEMM_SMEM_B>>>(x, W, a_src, a_dst, n);
    k_hist   <<<((E + 3) / 4 + 255) / 256, 256>>>(ei, E);
    k_scan_a <<<nb, 256>>>(n);
    k_scan_b <<<1, 128>>>(nb);
    k_scan_c <<<nb, 256>>>(n);
    k_permute<<<((E + 1) / 2 + 255) / 256, 256>>>(ei, E);
    k_accum  <<<(n * 32 + 255) / 256, 256>>>(out, n);
}

// round 5
// speedup vs baseline: 1.7615x; 1.4480x over previous
#include <cuda_runtime.h>
#include <cuda_fp16.h>
#include <cstdint>

// Problem constants (N=100000, E=1600000, IN_DIM=128, H=4, D=16)
#define MAX_N 100000
#define MAX_E 1600000
#define HD    64
#define KD    128
#define NHEAD 4

// ---------------- device scratch (static; no cudaMalloc allowed) -------------
__device__ __half g_h16[MAX_N * HD];     // projected features [N,64] fp16
__device__ float4 g_ss [MAX_N];          // per-node src scores [N,4]
__device__ float4 g_sd [MAX_N];          // per-node dst scores [N,4]
__device__ int    g_cnt[MAX_N];          // in-degree histogram
__device__ int    g_off[MAX_N];          // exclusive prefix (mutated by permute)
__device__ int    g_bsum[128];           // scan block sums
__device__ int    g_boff[128];           // scan block offsets
__device__ int    g_src_sorted[MAX_E];   // src node id, binned by dst
__device__ float4 g_exp_sorted[MAX_E];   // exp(leaky(e)) per head, binned by dst

// ---------------- helpers -----------------------------------------------------
__device__ __forceinline__ uint32_t smem_u32(const void* p) {
    uint32_t a;
    asm("{ .reg .u64 t; cvta.to.shared.u64 t, %1; cvt.u32.u64 %0, t; }"
        : "=r"(a) : "l"(p));
    return a;
}
__device__ __forceinline__ uint32_t f2h2(float a, float b) {
    __half2 h = __floats2half2_rn(a, b);         // low = a, high = b
    return *reinterpret_cast<uint32_t*>(&h);
}

// ---------------- init: zero histogram ---------------------------------------
__global__ void k_init(int n) {
    int i = blockIdx.x * blockDim.x + threadIdx.x;
    if (i < n) g_cnt[i] = 0;
}

// ---------------- GEMM via mma.sync (fp16 in, fp32 acc) + fused scores -------
// Block: 256 threads (8 warps). Tile: 128 rows x 64 cols x K=128.
// Warp w owns output cols [w*8, w*8+8). x is converted fp32->fp16 into a
// swizzled smem tile (16B-chunk XOR swizzle -> conflict-free ldmatrix).
__global__ void __launch_bounds__(256) k_gemm(const float* __restrict__ x,
                                              const float* __restrict__ W,
                                              const float* __restrict__ a_src,
                                              const float* __restrict__ a_dst,
                                              int n) {
    extern __shared__ __half xsm[];              // [128][128] fp16, swizzled
    __shared__ float sb1[128 * NHEAD];           // score accum: h . a_src
    __shared__ float sb2[128 * NHEAD];           // score accum: h . a_dst
    const int tid  = threadIdx.x;
    const int row0 = blockIdx.x * 128;
    const int lane = tid & 31;
    const int warp = tid >> 5;
    const int g    = lane >> 2;                  // groupID
    const int ct   = lane & 3;                   // thread-in-group

    // FIX(R4): 256 threads must cover all 512 entries.
#pragma unroll
    for (int i = tid; i < 512; i += 256) { sb1[i] = 0.f; sb2[i] = 0.f; }

    // ---- load x tile (128x128 fp32), convert to fp16, store swizzled ----
    const uint32_t xs_base = smem_u32(xsm);
#pragma unroll
    for (int it = 0; it < 8; it++) {
        int ci  = it * 256 + tid;
        int r   = ci >> 4;                       // row in tile
        int c   = ci & 15;                       // chunk in row
        int row = row0 + r;
        float4 v0 = make_float4(0.f, 0.f, 0.f, 0.f), v1 = v0;
        if (row < n) {
            v0 = ((const float4*)x)[row * 32 + c * 2];
            v1 = ((const float4*)x)[row * 32 + c * 2 + 1];
        }
        uint4 pk;
        pk.x = f2h2(v0.x, v0.y); pk.y = f2h2(v0.z, v0.w);
        pk.z = f2h2(v1.x, v1.y); pk.w = f2h2(v1.z, v1.w);
        int phys = c ^ (r & 7);
        *(uint4*)((char*)xsm + r * 256 + phys * 16) = pk;
    }

    // ---- B fragments: W rows [warp*8, warp*8+8), all 8 k-steps, in regs ----
    uint32_t bf[8][2];
    {
        const float* wp = W + (warp * 8 + g) * KD + ct * 2;
#pragma unroll
        for (int ks = 0; ks < 8; ks++) {
            float2 lo = *(const float2*)(wp + ks * 16);
            float2 hi = *(const float2*)(wp + ks * 16 + 8);
            bf[ks][0] = f2h2(lo.x, lo.y);
            bf[ks][1] = f2h2(hi.x, hi.y);
        }
    }
    __syncthreads();

    // ---- main loop: 8 k-steps x 8 m-tiles of m16n8k16 ----
    float acc[8][4] = {};
#pragma unroll
    for (int ks = 0; ks < 8; ks++) {
#pragma unroll
        for (int mt = 0; mt < 8; mt++) {
            int r     = mt * 16 + (lane & 15);
            int chunk = ks * 2 + (lane >> 4);
            int phys  = chunk ^ (r & 7);
            uint32_t addr = xs_base + r * 256 + phys * 16;
            uint32_t a0, a1, a2, a3;
            asm volatile(
                "ldmatrix.sync.aligned.m8n8.x4.shared.b16 {%0,%1,%2,%3}, [%4];"
                : "=r"(a0), "=r"(a1), "=r"(a2), "=r"(a3) : "r"(addr));
            asm volatile(
                "mma.sync.aligned.m16n8k16.row.col.f32.f16.f16.f32 "
                "{%0,%1,%2,%3}, {%4,%5,%6,%7}, {%8,%9}, {%0,%1,%2,%3};"
                : "+f"(acc[mt][0]), "+f"(acc[mt][1]),
                  "+f"(acc[mt][2]), "+f"(acc[mt][3])
                : "r"(a0), "r"(a1), "r"(a2), "r"(a3),
                  "r"(bf[ks][0]), "r"(bf[ks][1]));
        }
    }

    // ---- epilogue: write h (fp16) + fused attention scores ----
    const int head = warp >> 1;                  // cols [head*16, head*16+16)
    const int dofs = (warp & 1) * 8 + ct * 2;    // d within head
    const float as0 = __ldg(&a_src[head * 16 + dofs]);
    const float as1 = __ldg(&a_src[head * 16 + dofs + 1]);
    const float ad0 = __ldg(&a_dst[head * 16 + dofs]);
    const float ad1 = __ldg(&a_dst[head * 16 + dofs + 1]);
    uint32_t* h2out = (uint32_t*)g_h16;          // half2 units
    const int colh2 = warp * 4 + ct;             // (warp*8 + ct*2)/2

#pragma unroll
    for (int mt = 0; mt < 8; mt++) {
        int rA = row0 + mt * 16 + g;
        int rB = rA + 8;
        if (rA < n) h2out[rA * 32 + colh2] = f2h2(acc[mt][0], acc[mt][1]);
        if (rB < n) h2out[rB * 32 + colh2] = f2h2(acc[mt][2], acc[mt][3]);

        float s1a = acc[mt][0] * as0 + acc[mt][1] * as1;
        float s1b = acc[mt][2] * as0 + acc[mt][3] * as1;
        float s2a = acc[mt][0] * ad0 + acc[mt][1] * ad1;
        float s2b = acc[mt][2] * ad0 + acc[mt][3] * ad1;
#pragma unroll
        for (int d = 1; d <= 2; d <<= 1) {
            s1a += __shfl_xor_sync(0xffffffffu, s1a, d);
            s1b += __shfl_xor_sync(0xffffffffu, s1b, d);
            s2a += __shfl_xor_sync(0xffffffffu, s2a, d);
            s2b += __shfl_xor_sync(0xffffffffu, s2b, d);
        }
        if (ct == 0) {
            int mA = mt * 16 + g;
            atomicAdd(&sb1[mA * NHEAD + head], s1a);
            atomicAdd(&sb1[(mA + 8) * NHEAD + head], s1b);
            atomicAdd(&sb2[mA * NHEAD + head], s2a);
            atomicAdd(&sb2[(mA + 8) * NHEAD + head], s2b);
        }
    }
    __syncthreads();
    // FIX(R4): 256 threads must write all 512 (node, head) scores.
#pragma unroll
    for (int i = tid; i < 512; i += 256) {
        int node = row0 + (i >> 2);
        if (node < n) {
            ((float*)g_ss)[node * NHEAD + (i & 3)] = sb1[i];
            ((float*)g_sd)[node * NHEAD + (i & 3)] = sb2[i];
        }
    }
}

// ---------------- in-degree histogram (4 independent REDs per thread) --------
__global__ void k_hist(const int* __restrict__ ei, int E) {
    int t = blockIdx.x * blockDim.x + threadIdx.x;
    if ((E & 3) == 0) {
        int i4 = t * 4;
        if (i4 >= E) return;
        int4 d = *(const int4*)&ei[E + i4];
        atomicAdd(&g_cnt[d.x], 1);
        atomicAdd(&g_cnt[d.y], 1);
        atomicAdd(&g_cnt[d.z], 1);
        atomicAdd(&g_cnt[d.w], 1);
    } else {
        int i4 = t * 4;
#pragma unroll
        for (int j = 0; j < 4; j++)
            if (i4 + j < E) atomicAdd(&g_cnt[ei[E + i4 + j]], 1);
    }
}

// ---------------- exclusive scan (3 kernels; chunk = 1024) -------------------
__global__ void k_scan_a(int n) {
    __shared__ int warp_tot[8];
    int b = blockIdx.x, t = threadIdx.x;
    int idx0 = b * 1024 + t * 4;
    int s = 0;
#pragma unroll
    for (int j = 0; j < 4; j++) { int i = idx0 + j; if (i < n) s += g_cnt[i]; }
#pragma unroll
    for (int d = 16; d; d >>= 1) s += __shfl_down_sync(0xffffffffu, s, d);
    if ((t & 31) == 0) warp_tot[t >> 5] = s;
    __syncthreads();
    if (t == 0) {
        int tot = 0;
#pragma unroll
        for (int w = 0; w < 8; w++) tot += warp_tot[w];
        g_bsum[b] = tot;
    }
}

__global__ void k_scan_b(int nb) {
    __shared__ int wt[4];
    int t = threadIdx.x;
    int v = (t < nb) ? g_bsum[t] : 0;
    int lane = t & 31, w = t >> 5;
    int inc = v;
#pragma unroll
    for (int d = 1; d < 32; d <<= 1) {
        int o = __shfl_up_sync(0xffffffffu, inc, d);
        if (lane >= d) inc += o;
    }
    if (lane == 31) wt[w] = inc;
    __syncthreads();
    if (t == 0) {
        int s = 0;
#pragma unroll
        for (int i = 0; i < 4; i++) { int x = wt[i]; wt[i] = s; s += x; }
    }
    __syncthreads();
    int excl = wt[w] + inc - v;
    if (t < nb) g_boff[t] = excl;
}

__global__ void k_scan_c(int n) {
    __shared__ int warp_pre[8];
    __shared__ int blk_base;
    int b = blockIdx.x, t = threadIdx.x;
    int idx0 = b * 1024 + t * 4;
    int v[4];
#pragma unroll
    for (int j = 0; j < 4; j++) { int i = idx0 + j; v[j] = (i < n) ? g_cnt[i] : 0; }
    int tsum = v[0] + v[1] + v[2] + v[3];
    int lane = t & 31, w = t >> 5;
    int inc = tsum;
#pragma unroll
    for (int d = 1; d < 32; d <<= 1) {
        int o = __shfl_up_sync(0xffffffffu, inc, d);
        if (lane >= d) inc += o;
    }
    if (lane == 31) warp_pre[w] = inc;
    __syncthreads();
    if (t == 0) {
        int s = 0;
#pragma unroll
        for (int ww = 0; ww < 8; ww++) { int x = warp_pre[ww]; warp_pre[ww] = s; s += x; }
        blk_base = g_boff[b];
    }
    __syncthreads();
    int excl = blk_base + warp_pre[w] + (inc - tsum);
#pragma unroll
    for (int j = 0; j < 4; j++) {
        int i = idx0 + j;
        if (i < n) g_off[i] = excl;
        excl += v[j];
    }
}

// ---------------- permute: bin edges by dst, precompute exp(leaky(e)) --------
__device__ __forceinline__ void permute_one(int src, int dst) {
    float4 s4 = g_ss[src];
    float4 d4 = g_sd[dst];
    float4 ee;
    float s;
    s = s4.x + d4.x; s = (s > 0.f) ? s : 0.2f * s; ee.x = __expf(s);
    s = s4.y + d4.y; s = (s > 0.f) ? s : 0.2f * s; ee.y = __expf(s);
    s = s4.z + d4.z; s = (s > 0.f) ? s : 0.2f * s; ee.z = __expf(s);
    s = s4.w + d4.w; s = (s > 0.f) ? s : 0.2f * s; ee.w = __expf(s);
    int pos = atomicAdd(&g_off[dst], 1);
    g_src_sorted[pos] = src;
    g_exp_sorted[pos] = ee;
}

__global__ void k_permute(const int* __restrict__ ei, int E) {
    int p = blockIdx.x * blockDim.x + threadIdx.x;
    if ((E & 1) == 0) {
        int e0 = p * 2;
        if (e0 >= E) return;
        int2 sv = *(const int2*)&ei[e0];
        int2 dv = *(const int2*)&ei[E + e0];
        permute_one(sv.x, dv.x);
        permute_one(sv.y, dv.y);
    } else {
        int e0 = p * 2;
#pragma unroll
        for (int j = 0; j < 2; j++)
            if (e0 + j < E) permute_one(ei[e0 + j], ei[E + e0 + j]);
    }
}

// ---------------- pull accumulate: one warp per node, fp16 h gather ----------
__global__ void k_accum(float* __restrict__ out, int n) {
    int warp = (blockIdx.x * blockDim.x + threadIdx.x) >> 5;
    if (warp >= n) return;
    int lane = threadIdx.x & 31;
    int j    = lane >> 4;          // edge slot 0/1
    int l    = lane & 15;          // component group: head*4 + q (4 cols)
    int head = l >> 2;
    int start = warp ? g_off[warp - 1] : 0;   // g_off holds end offsets now
    int end   = g_off[warp];

    float4 acc = make_float4(0.f, 0.f, 0.f, 0.f);
    float sume = 0.f;
    const float* exps = (const float*)g_exp_sorted;
    const uint2* h16  = (const uint2*)g_h16;   // 4 halfs per lane-component
#pragma unroll 2
    for (int e = start + j; e < end; e += 2) {
        int   src  = __ldg(&g_src_sorted[e]);
        float expe = __ldg(&exps[e * 4 + head]);
        uint2 raw  = __ldg(&h16[src * 16 + l]);
        float2 f0  = __half22float2(*(const __half2*)&raw.x);
        float2 f1  = __half22float2(*(const __half2*)&raw.y);
        acc.x = fmaf(f0.x, expe, acc.x);
        acc.y = fmaf(f0.y, expe, acc.y);
        acc.z = fmaf(f1.x, expe, acc.z);
        acc.w = fmaf(f1.y, expe, acc.w);
        sume += expe;
    }
    acc.x += __shfl_xor_sync(0xffffffffu, acc.x, 16);
    acc.y += __shfl_xor_sync(0xffffffffu, acc.y, 16);
    acc.z += __shfl_xor_sync(0xffffffffu, acc.z, 16);
    acc.w += __shfl_xor_sync(0xffffffffu, acc.w, 16);
    sume  += __shfl_xor_sync(0xffffffffu, sume, 16);
    if (j == 0) {
        float r = 1.f / fmaxf(sume, 1e-9f);
        ((float4*)out)[warp * 16 + l] =
            make_float4(acc.x * r, acc.y * r, acc.z * r, acc.w * r);
    }
}

// ---------------- launch ------------------------------------------------------
extern "C" void kernel_launch(void* const* d_in, const int* in_sizes, int n_in,
                              void* d_out, int out_size) {
    const float* x     = (const float*)d_in[0];
    const float* W     = (const float*)d_in[1];
    const float* a_src = (const float*)d_in[2];
    const float* a_dst = (const float*)d_in[3];
    const int*   ei    = (const int*)d_in[4];
    float*       out   = (float*)d_out;

    const int n = in_sizes[0] / KD;
    const int E = in_sizes[4] / 2;
    const int nb = (n + 1023) / 1024;     // scan blocks (<=128)

    k_init   <<<(n + 255) / 256, 256>>>(n);
    k_gemm   <<<(n + 127) / 128, 256, 128 * 128 * 2>>>(x, W, a_src, a_dst, n);
    k_hist   <<<((E + 3) / 4 + 255) / 256, 256>>>(ei, E);
    k_scan_a <<<nb, 256>>>(n);
    k_scan_b <<<1, 128>>>(nb);
    k_scan_c <<<nb, 256>>>(n);
    k_permute<<<((E + 1) / 2 + 255) / 256, 256>>>(ei, E);
    k_accum  <<<(n * 32 + 255) / 256, 256>>>(out, n);
}

// round 6
// speedup vs baseline: 1.8565x; 1.0539x over previous
#include <cuda_runtime.h>
#include <cuda_fp16.h>
#include <cstdint>

// Problem constants (N=100000, E=1600000, IN_DIM=128, H=4, D=16)
#define MAX_N 100000
#define MAX_E 1600000
#define HD    64
#define KD    128
#define NHEAD 4

// ---------------- device scratch (static; no cudaMalloc allowed) -------------
__device__ __half g_h16[MAX_N * HD];     // projected features [N,64] fp16
__device__ float4 g_ss [MAX_N];          // per-node src scores [N,4]
__device__ float4 g_sd [MAX_N];          // per-node dst scores [N,4]
__device__ int    g_cnt[MAX_N];          // in-degree histogram
__device__ int    g_off[MAX_N];          // exclusive prefix (mutated by permute)
__device__ int    g_bsum[128];           // scan block sums
__device__ int    g_boff[128];           // scan block offsets
__device__ int    g_src_sorted[MAX_E];   // src node id, binned by dst
__device__ float4 g_exp_sorted[MAX_E];   // exp(leaky(e)) per head, binned by dst

// ---------------- helpers -----------------------------------------------------
__device__ __forceinline__ uint32_t smem_u32(const void* p) {
    uint32_t a;
    asm("{ .reg .u64 t; cvta.to.shared.u64 t, %1; cvt.u32.u64 %0, t; }"
        : "=r"(a) : "l"(p));
    return a;
}
__device__ __forceinline__ uint32_t f2h2(float a, float b) {
    __half2 h = __floats2half2_rn(a, b);         // low = a, high = b
    return *reinterpret_cast<uint32_t*>(&h);
}

// ---------------- init: zero histogram ---------------------------------------
__global__ void k_init(int n) {
    int i = blockIdx.x * blockDim.x + threadIdx.x;
    if (i < n) g_cnt[i] = 0;
}

// ---------------- GEMM via mma.sync (fp16 in, fp32 acc) + fused scores -------
__global__ void __launch_bounds__(256) k_gemm(const float* __restrict__ x,
                                              const float* __restrict__ W,
                                              const float* __restrict__ a_src,
                                              const float* __restrict__ a_dst,
                                              int n) {
    extern __shared__ __half xsm[];              // [128][128] fp16, swizzled
    __shared__ float sb1[128 * NHEAD];           // score accum: h . a_src
    __shared__ float sb2[128 * NHEAD];           // score accum: h . a_dst
    const int tid  = threadIdx.x;
    const int row0 = blockIdx.x * 128;
    const int lane = tid & 31;
    const int warp = tid >> 5;
    const int g    = lane >> 2;                  // groupID
    const int ct   = lane & 3;                   // thread-in-group

#pragma unroll
    for (int i = tid; i < 512; i += 256) { sb1[i] = 0.f; sb2[i] = 0.f; }

    const uint32_t xs_base = smem_u32(xsm);
#pragma unroll
    for (int it = 0; it < 8; it++) {
        int ci  = it * 256 + tid;
        int r   = ci >> 4;
        int c   = ci & 15;
        int row = row0 + r;
        float4 v0 = make_float4(0.f, 0.f, 0.f, 0.f), v1 = v0;
        if (row < n) {
            v0 = ((const float4*)x)[row * 32 + c * 2];
            v1 = ((const float4*)x)[row * 32 + c * 2 + 1];
        }
        uint4 pk;
        pk.x = f2h2(v0.x, v0.y); pk.y = f2h2(v0.z, v0.w);
        pk.z = f2h2(v1.x, v1.y); pk.w = f2h2(v1.z, v1.w);
        int phys = c ^ (r & 7);
        *(uint4*)((char*)xsm + r * 256 + phys * 16) = pk;
    }

    uint32_t bf[8][2];
    {
        const float* wp = W + (warp * 8 + g) * KD + ct * 2;
#pragma unroll
        for (int ks = 0; ks < 8; ks++) {
            float2 lo = *(const float2*)(wp + ks * 16);
            float2 hi = *(const float2*)(wp + ks * 16 + 8);
            bf[ks][0] = f2h2(lo.x, lo.y);
            bf[ks][1] = f2h2(hi.x, hi.y);
        }
    }
    __syncthreads();

    float acc[8][4] = {};
#pragma unroll
    for (int ks = 0; ks < 8; ks++) {
#pragma unroll
        for (int mt = 0; mt < 8; mt++) {
            int r     = mt * 16 + (lane & 15);
            int chunk = ks * 2 + (lane >> 4);
            int phys  = chunk ^ (r & 7);
            uint32_t addr = xs_base + r * 256 + phys * 16;
            uint32_t a0, a1, a2, a3;
            asm volatile(
                "ldmatrix.sync.aligned.m8n8.x4.shared.b16 {%0,%1,%2,%3}, [%4];"
                : "=r"(a0), "=r"(a1), "=r"(a2), "=r"(a3) : "r"(addr));
            asm volatile(
                "mma.sync.aligned.m16n8k16.row.col.f32.f16.f16.f32 "
                "{%0,%1,%2,%3}, {%4,%5,%6,%7}, {%8,%9}, {%0,%1,%2,%3};"
                : "+f"(acc[mt][0]), "+f"(acc[mt][1]),
                  "+f"(acc[mt][2]), "+f"(acc[mt][3])
                : "r"(a0), "r"(a1), "r"(a2), "r"(a3),
                  "r"(bf[ks][0]), "r"(bf[ks][1]));
        }
    }

    const int head = warp >> 1;
    const int dofs = (warp & 1) * 8 + ct * 2;
    const float as0 = __ldg(&a_src[head * 16 + dofs]);
    const float as1 = __ldg(&a_src[head * 16 + dofs + 1]);
    const float ad0 = __ldg(&a_dst[head * 16 + dofs]);
    const float ad1 = __ldg(&a_dst[head * 16 + dofs + 1]);
    uint32_t* h2out = (uint32_t*)g_h16;
    const int colh2 = warp * 4 + ct;

#pragma unroll
    for (int mt = 0; mt < 8; mt++) {
        int rA = row0 + mt * 16 + g;
        int rB = rA + 8;
        if (rA < n) h2out[rA * 32 + colh2] = f2h2(acc[mt][0], acc[mt][1]);
        if (rB < n) h2out[rB * 32 + colh2] = f2h2(acc[mt][2], acc[mt][3]);

        float s1a = acc[mt][0] * as0 + acc[mt][1] * as1;
        float s1b = acc[mt][2] * as0 + acc[mt][3] * as1;
        float s2a = acc[mt][0] * ad0 + acc[mt][1] * ad1;
        float s2b = acc[mt][2] * ad0 + acc[mt][3] * ad1;
#pragma unroll
        for (int d = 1; d <= 2; d <<= 1) {
            s1a += __shfl_xor_sync(0xffffffffu, s1a, d);
            s1b += __shfl_xor_sync(0xffffffffu, s1b, d);
            s2a += __shfl_xor_sync(0xffffffffu, s2a, d);
            s2b += __shfl_xor_sync(0xffffffffu, s2b, d);
        }
        if (ct == 0) {
            int mA = mt * 16 + g;
            atomicAdd(&sb1[mA * NHEAD + head], s1a);
            atomicAdd(&sb1[(mA + 8) * NHEAD + head], s1b);
            atomicAdd(&sb2[mA * NHEAD + head], s2a);
            atomicAdd(&sb2[(mA + 8) * NHEAD + head], s2b);
        }
    }
    __syncthreads();
#pragma unroll
    for (int i = tid; i < 512; i += 256) {
        int node = row0 + (i >> 2);
        if (node < n) {
            ((float*)g_ss)[node * NHEAD + (i & 3)] = sb1[i];
            ((float*)g_sd)[node * NHEAD + (i & 3)] = sb2[i];
        }
    }
}

// ---------------- in-degree histogram (4 independent REDs per thread) --------
__global__ void k_hist(const int* __restrict__ ei, int E) {
    int t = blockIdx.x * blockDim.x + threadIdx.x;
    if ((E & 3) == 0) {
        int i4 = t * 4;
        if (i4 >= E) return;
        int4 d = *(const int4*)&ei[E + i4];
        atomicAdd(&g_cnt[d.x], 1);
        atomicAdd(&g_cnt[d.y], 1);
        atomicAdd(&g_cnt[d.z], 1);
        atomicAdd(&g_cnt[d.w], 1);
    } else {
        int i4 = t * 4;
#pragma unroll
        for (int j = 0; j < 4; j++)
            if (i4 + j < E) atomicAdd(&g_cnt[ei[E + i4 + j]], 1);
    }
}

// ---------------- exclusive scan (3 kernels; chunk = 1024) -------------------
__global__ void k_scan_a(int n) {
    __shared__ int warp_tot[8];
    int b = blockIdx.x, t = threadIdx.x;
    int idx0 = b * 1024 + t * 4;
    int s = 0;
#pragma unroll
    for (int j = 0; j < 4; j++) { int i = idx0 + j; if (i < n) s += g_cnt[i]; }
#pragma unroll
    for (int d = 16; d; d >>= 1) s += __shfl_down_sync(0xffffffffu, s, d);
    if ((t & 31) == 0) warp_tot[t >> 5] = s;
    __syncthreads();
    if (t == 0) {
        int tot = 0;
#pragma unroll
        for (int w = 0; w < 8; w++) tot += warp_tot[w];
        g_bsum[b] = tot;
    }
}

__global__ void k_scan_b(int nb) {
    __shared__ int wt[4];
    int t = threadIdx.x;
    int v = (t < nb) ? g_bsum[t] : 0;
    int lane = t & 31, w = t >> 5;
    int inc = v;
#pragma unroll
    for (int d = 1; d < 32; d <<= 1) {
        int o = __shfl_up_sync(0xffffffffu, inc, d);
        if (lane >= d) inc += o;
    }
    if (lane == 31) wt[w] = inc;
    __syncthreads();
    if (t == 0) {
        int s = 0;
#pragma unroll
        for (int i = 0; i < 4; i++) { int x = wt[i]; wt[i] = s; s += x; }
    }
    __syncthreads();
    int excl = wt[w] + inc - v;
    if (t < nb) g_boff[t] = excl;
}

__global__ void k_scan_c(int n) {
    __shared__ int warp_pre[8];
    __shared__ int blk_base;
    int b = blockIdx.x, t = threadIdx.x;
    int idx0 = b * 1024 + t * 4;
    int v[4];
#pragma unroll
    for (int j = 0; j < 4; j++) { int i = idx0 + j; v[j] = (i < n) ? g_cnt[i] : 0; }
    int tsum = v[0] + v[1] + v[2] + v[3];
    int lane = t & 31, w = t >> 5;
    int inc = tsum;
#pragma unroll
    for (int d = 1; d < 32; d <<= 1) {
        int o = __shfl_up_sync(0xffffffffu, inc, d);
        if (lane >= d) inc += o;
    }
    if (lane == 31) warp_pre[w] = inc;
    __syncthreads();
    if (t == 0) {
        int s = 0;
#pragma unroll
        for (int ww = 0; ww < 8; ww++) { int x = warp_pre[ww]; warp_pre[ww] = s; s += x; }
        blk_base = g_boff[b];
    }
    __syncthreads();
    int excl = blk_base + warp_pre[w] + (inc - tsum);
#pragma unroll
    for (int j = 0; j < 4; j++) {
        int i = idx0 + j;
        if (i < n) g_off[i] = excl;
        excl += v[j];
    }
}

// ---------------- permute: bin edges by dst, precompute exp(leaky(e)) --------
__device__ __forceinline__ void permute_one(int src, int dst) {
    float4 s4 = g_ss[src];
    float4 d4 = g_sd[dst];
    float4 ee;
    float s;
    s = s4.x + d4.x; s = (s > 0.f) ? s : 0.2f * s; ee.x = __expf(s);
    s = s4.y + d4.y; s = (s > 0.f) ? s : 0.2f * s; ee.y = __expf(s);
    s = s4.z + d4.z; s = (s > 0.f) ? s : 0.2f * s; ee.z = __expf(s);
    s = s4.w + d4.w; s = (s > 0.f) ? s : 0.2f * s; ee.w = __expf(s);
    int pos = atomicAdd(&g_off[dst], 1);
    g_src_sorted[pos] = src;
    g_exp_sorted[pos] = ee;
}

__global__ void k_permute(const int* __restrict__ ei, int E) {
    int p = blockIdx.x * blockDim.x + threadIdx.x;
    if ((E & 1) == 0) {
        int e0 = p * 2;
        if (e0 >= E) return;
        int2 sv = *(const int2*)&ei[e0];
        int2 dv = *(const int2*)&ei[E + e0];
        permute_one(sv.x, dv.x);
        permute_one(sv.y, dv.y);
    } else {
        int e0 = p * 2;
#pragma unroll
        for (int j = 0; j < 2; j++)
            if (e0 + j < E) permute_one(ei[e0 + j], ei[E + e0 + j]);
    }
}

// ---------------- pull accumulate: one warp per node, 4 edges in flight ------
// 32 lanes = 4 edge-slots x 8 lanes; each lane gathers 16B (uint4 = 8 halfs).
__global__ void k_accum(float* __restrict__ out, int n) {
    int warp = (blockIdx.x * blockDim.x + threadIdx.x) >> 5;
    if (warp >= n) return;
    int lane = threadIdx.x & 31;
    int slot = lane >> 3;          // edge slot 0..3
    int sub  = lane & 7;           // 8 halfs per lane: cols sub*8..sub*8+7
    int head = sub >> 1;           // col/16
    int start = warp ? g_off[warp - 1] : 0;   // g_off holds end offsets now
    int end   = g_off[warp];

    float a0 = 0.f, a1 = 0.f, a2 = 0.f, a3 = 0.f;
    float a4 = 0.f, a5 = 0.f, a6 = 0.f, a7 = 0.f;
    float sume = 0.f;
    const float* exps = (const float*)g_exp_sorted;
    const uint4* h16  = (const uint4*)g_h16;   // 8 halfs per element
#pragma unroll 2
    for (int e = start + slot; e < end; e += 4) {
        int   src  = __ldg(&g_src_sorted[e]);
        float expe = __ldg(&exps[e * 4 + head]);
        uint4 raw  = __ldg(&h16[src * 8 + sub]);
        float2 f0  = __half22float2(*(const __half2*)&raw.x);
        float2 f1  = __half22float2(*(const __half2*)&raw.y);
        float2 f2  = __half22float2(*(const __half2*)&raw.z);
        float2 f3  = __half22float2(*(const __half2*)&raw.w);
        a0 = fmaf(f0.x, expe, a0); a1 = fmaf(f0.y, expe, a1);
        a2 = fmaf(f1.x, expe, a2); a3 = fmaf(f1.y, expe, a3);
        a4 = fmaf(f2.x, expe, a4); a5 = fmaf(f2.y, expe, a5);
        a6 = fmaf(f3.x, expe, a6); a7 = fmaf(f3.y, expe, a7);
        sume += expe;
    }
    // combine the 4 edge slots (lanes sub stay aligned across slots)
#pragma unroll
    for (int d = 8; d <= 16; d <<= 1) {
        a0 += __shfl_xor_sync(0xffffffffu, a0, d);
        a1 += __shfl_xor_sync(0xffffffffu, a1, d);
        a2 += __shfl_xor_sync(0xffffffffu, a2, d);
        a3 += __shfl_xor_sync(0xffffffffu, a3, d);
        a4 += __shfl_xor_sync(0xffffffffu, a4, d);
        a5 += __shfl_xor_sync(0xffffffffu, a5, d);
        a6 += __shfl_xor_sync(0xffffffffu, a6, d);
        a7 += __shfl_xor_sync(0xffffffffu, a7, d);
        sume += __shfl_xor_sync(0xffffffffu, sume, d);
    }
    if (slot == 0) {
        float r = 1.f / fmaxf(sume, 1e-9f);
        float4* o4 = (float4*)out + warp * 16 + sub * 2;
        o4[0] = make_float4(a0 * r, a1 * r, a2 * r, a3 * r);
        o4[1] = make_float4(a4 * r, a5 * r, a6 * r, a7 * r);
    }
}

// ---------------- launch: fork edge-binning || GEMM, join before permute -----
extern "C" void kernel_launch(void* const* d_in, const int* in_sizes, int n_in,
                              void* d_out, int out_size) {
    const float* x     = (const float*)d_in[0];
    const float* W     = (const float*)d_in[1];
    const float* a_src = (const float*)d_in[2];
    const float* a_dst = (const float*)d_in[3];
    const int*   ei    = (const int*)d_in[4];
    float*       out   = (float*)d_out;

    const int n = in_sizes[0] / KD;
    const int E = in_sizes[4] / 2;
    const int nb = (n + 1023) / 1024;

    static cudaStream_t s2 = nullptr;
    static cudaEvent_t evFork = nullptr, evJoin = nullptr;
    if (!s2) {
        cudaStreamCreateWithFlags(&s2, cudaStreamNonBlocking);
        cudaEventCreateWithFlags(&evFork, cudaEventDisableTiming);
        cudaEventCreateWithFlags(&evJoin, cudaEventDisableTiming);
    }

    // Fork: edge binning chain on s2, GEMM on the main stream (independent data).
    cudaEventRecord(evFork, 0);
    cudaStreamWaitEvent(s2, evFork, 0);

    k_init   <<<(n + 255) / 256, 256, 0, s2>>>(n);
    k_hist   <<<((E + 3) / 4 + 255) / 256, 256, 0, s2>>>(ei, E);
    k_scan_a <<<nb, 256, 0, s2>>>(n);
    k_scan_b <<<1, 128, 0, s2>>>(nb);
    k_scan_c <<<nb, 256, 0, s2>>>(n);
    cudaEventRecord(evJoin, s2);

    k_gemm   <<<(n + 127) / 128, 256, 128 * 128 * 2>>>(x, W, a_src, a_dst, n);

    // Join: permute needs scores (main) + offsets (s2).
    cudaStreamWaitEvent(0, evJoin, 0);
    k_permute<<<((E + 1) / 2 + 255) / 256, 256>>>(ei, E);
    k_accum  <<<(n * 32 + 255) / 256, 256>>>(out, n);
}